// round 12
// baseline (speedup 1.0000x reference)
#include <cuda_runtime.h>
#include <cuda_fp16.h>
#include <math.h>
#include <stdint.h>

#define B_DIM 64
#define T_DIM 1024
#define H_DIM 512
#define GRID  128
#define BLK   1024
#define NPAIR 40

// ---- smem byte offsets ----
#define BF_B    0         // U-pair B-frags fp16: [nt10][kt32][lane32][8B] = 81920
#define BEXT_B  81920     // ext B-frags fp16: [nt10][ek4][lane32][8B] = 10240
#define WAS_B   92160     // W_a B-frags fp16: [kl32][n16 2][lane32][16B] = 32768
#define BIAS_B  124928    // 80 floats
#define UBUF_B  125248    // 72x32 fp32 = 9216
#define ASTG_B  134528    // A-stage double buffer 2x32KB
#define SMEM_BYTES 200064

// ---- device scratch ----
__device__ uint32_t g_hp[32 * 4 * 32 * 8];          // h A-frags fp16 split
__device__ uint32_t g_lp[8 * 32 * 5 * 32 * 8];      // l A-frags fp16 split
__device__ uint32_t g_ep[1024u * 4 * 4 * 32 * 8];   // ext A-frags fp16 split
__device__ float g_c[B_DIM * H_DIM];
__device__ float g_l[B_DIM * 9 * H_DIM];
__device__ float g_f[B_DIM * H_DIM];
__device__ float g_o[B_DIM * H_DIM];
__device__ unsigned g_bar_count = 0;
__device__ volatile unsigned g_bar_gen = 0;

struct Params {
    const float* U[20];
    const float* W[20];
    const float* bb[20];
    const float* Y;
    const float* x[8];
    const float* W_a;
    const float* b_a;
};

// ---- fast activations (MUFU) ----
__device__ __forceinline__ float tanh_fast(float z) {
    float r; asm("tanh.approx.f32 %0, %1;" : "=f"(r) : "f"(z)); return r;
}
__device__ __forceinline__ float exp_fast(float z) {
    float r; asm("ex2.approx.ftz.f32 %0, %1;" : "=f"(r) : "f"(z * 1.4426950408889634f));
    return r;
}
__device__ __forceinline__ float sig_fast(float z) {
    float ex; asm("ex2.approx.ftz.f32 %0, %1;" : "=f"(ex) : "f"(z * -1.4426950408889634f));
    float r;  asm("rcp.approx.ftz.f32 %0, %1;" : "=f"(r) : "f"(1.0f + ex));
    return r;
}

__device__ __forceinline__ void cvt_pair_h(float v0, float v1, uint32_t& hi, uint32_t& lo)
{
    const __half h0 = __float2half_rn(v0), h1 = __float2half_rn(v1);
    const __half l0 = __float2half_rn(v0 - __half2float(h0));
    const __half l1 = __float2half_rn(v1 - __half2float(h1));
    hi = ((uint32_t)__half_as_ushort(h1) << 16) | __half_as_ushort(h0);
    lo = ((uint32_t)__half_as_ushort(l1) << 16) | __half_as_ushort(l0);
}

__device__ __forceinline__ void mma_h(float* d, const uint32_t* a, uint32_t b0, uint32_t b1)
{
    asm volatile(
        "mma.sync.aligned.m16n8k16.row.col.f32.f16.f16.f32 "
        "{%0,%1,%2,%3}, {%4,%5,%6,%7}, {%8,%9}, {%0,%1,%2,%3};"
        : "+f"(d[0]), "+f"(d[1]), "+f"(d[2]), "+f"(d[3])
        : "r"(a[0]), "r"(a[1]), "r"(a[2]), "r"(a[3]), "r"(b0), "r"(b1));
}

__device__ __forceinline__ void grid_barrier()
{
    __syncthreads();
    if (threadIdx.x == 0) {
        __threadfence();
        unsigned gen = g_bar_gen;
        if (atomicAdd(&g_bar_count, 1u) == (unsigned)(gridDim.x - 1)) {
            g_bar_count = 0;
            __threadfence();
            g_bar_gen = gen + 1;
            __threadfence();
        } else {
            while (g_bar_gen == gen) { }
            __threadfence();
        }
    }
    __syncthreads();
}

__device__ __forceinline__ int memA(int pt) { return pt == 0 ? 0 : (pt == 1 ? 1 : pt + 2); }
__device__ __forceinline__ int memB(int pt) { return pt == 0 ? 2 : (pt == 1 ? 3 : pt + 10); }

extern __shared__ float sm[];

__device__ __forceinline__ void copy_chunk(char* dst, const uint32_t* src_u32, int n_uint4, int tid)
{
    const uint4* src = (const uint4*)src_u32;
    for (int i = tid; i < n_uint4; i += BLK) {
        const uint4 v = __ldg(src + i);
        const int half = i & 1, lane2 = (i >> 1) & 31, km = i >> 6;
        *(uint4*)(dst + km * 1024 + lane2 * 32 + ((half * 16) ^ ((lane2 & 4) << 2))) = v;
    }
}

__global__ __launch_bounds__(BLK, 1) void lstm_h4(Params p, float* __restrict__ out,
                                                  int seq_off, int write_hT)
{
    const int tid = threadIdx.x;
    const int bid = blockIdx.x;
    const int lane = tid & 31;
    const int wid = tid >> 5;
    const int gtid = bid * BLK + tid;
    char* smc = (char*)sm;
    float* bias_sm = (float*)(smc + BIAS_B);
    float* ub = (float*)(smc + UBUF_B);
    char* astg = smc + ASTG_B;
    const uint32_t ho = lane * 32 + ((lane & 4) << 2);

    for (int i = gtid; i < 32 * 4 * 32 * 8; i += GRID * BLK) g_hp[i] = 0u;
    for (int i = gtid; i < 8 * 32 * 5 * 32 * 8; i += GRID * BLK) g_lp[i] = 0u;
    for (int i = gtid; i < B_DIM * H_DIM; i += GRID * BLK) g_c[i] = 0.0f;

    // ---- one-time: ext input A-frags (all t) ----
    for (int idx = gtid; idx < T_DIM * 2048; idx += GRID * BLK) {
        const int t = idx >> 11;
        const int r = idx & 2047;
        const int b = r >> 5, q = (r & 31) * 2;
        float v0, v1;
        {
            const int qq = q;
            if (qq < 32) v0 = p.Y[((size_t)b * 32 + qq) * T_DIM + t];
            else if (qq < 56) { const int rr = qq - 32, xk = rr / 3, i2 = rr - 3 * xk;
                                v0 = p.x[xk][((size_t)b * 3 + i2) * T_DIM + t]; }
            else v0 = 0.0f;
        }
        {
            const int qq = q + 1;
            if (qq < 32) v1 = p.Y[((size_t)b * 32 + qq) * T_DIM + t];
            else if (qq < 56) { const int rr = qq - 32, xk = rr / 3, i2 = rr - 3 * xk;
                                v1 = p.x[xk][((size_t)b * 3 + i2) * T_DIM + t]; }
            else v1 = 0.0f;
        }
        uint32_t hi, lo; cvt_pair_h(v0, v1, hi, lo);
        const int lane2 = (b & 7) * 4 + ((q & 7) >> 1);
        const int slot = ((b >> 3) & 1) * 2 + ((q & 15) >> 3);
        const size_t base = ((((size_t)t * 4 + (q >> 4)) * 4 + (b >> 4)) * 32 + lane2) * 8 + slot;
        g_ep[base] = hi; g_ep[base + 4] = lo;
    }

    // ---- one-time: U pair-columns -> fp16 B-frags (smem) ----
    for (int e = tid; e < 80 * H_DIM; e += BLK) {
        const int s = e >> 9, j = e & 511;
        const int pq = bid * NPAIR + (s >> 1);
        const int pt = pq >> 9, c = pq & 511;
        const int m = (s & 1) ? memB(pt) : memA(pt);
        const float v = p.U[m][(size_t)j * H_DIM + c];
        const uint32_t off = (uint32_t)(s >> 3) * 8192u + (uint32_t)(j >> 4) * 256u
                           + (uint32_t)((s & 7) * 4 + ((j & 7) >> 1)) * 8u
                           + (uint32_t)((j & 15) >> 3) * 4u + (uint32_t)(j & 1) * 2u;
        *(unsigned short*)(smc + BF_B + off) = __half_as_ushort(__float2half_rn(v));
    }
    for (int e = tid; e < 2560; e += BLK) ((uint32_t*)(smc + BEXT_B))[e] = 0u;
    __syncthreads();
    for (int e = tid; e < 80 * 32; e += BLK) {
        const int s = e >> 5, i = e & 31;
        const int pq = bid * NPAIR + (s >> 1);
        const int pt = pq >> 9, c = pq & 511;
        const int m = (s & 1) ? memB(pt) : memA(pt);
        float v; int q;
        if (m < 4) { v = p.W[m][(size_t)i * H_DIM + c]; q = i; }
        else {
            if (i >= 3) continue;
            const int k = (m < 12) ? (m - 4) : (m - 12);
            const int xsel = (m < 12) ? ((k == 0) ? 0 : 1) : k;
            v = p.W[m][(size_t)i * H_DIM + c];
            q = 32 + xsel * 3 + i;
        }
        const uint32_t off = (uint32_t)(s >> 3) * 1024u + (uint32_t)(q >> 4) * 256u
                           + (uint32_t)((s & 7) * 4 + ((q & 7) >> 1)) * 8u
                           + (uint32_t)((q & 15) >> 3) * 4u + (uint32_t)(q & 1) * 2u;
        *(unsigned short*)(smc + BEXT_B + off) = __half_as_ushort(__float2half_rn(v));
    }
    for (int s = tid; s < 80; s += BLK) {
        const int pq = bid * NPAIR + (s >> 1);
        const int pt = pq >> 9, c = pq & 511;
        bias_sm[s] = p.bb[(s & 1) ? memB(pt) : memA(pt)][c];
    }
    {
        const int Bhg_ = bid & 15;
        for (int e = tid; e < 16384; e += BLK) {
            const int j = e >> 5, h2 = e & 31;
            const float v = p.W_a[(size_t)j * H_DIM + Bhg_ * 32 + h2];
            const uint32_t off = (uint32_t)(j >> 4) * 1024u + (uint32_t)(h2 >> 4) * 512u
                               + (uint32_t)((h2 & 7) * 4 + ((j & 7) >> 1)) * 16u
                               + ((((uint32_t)h2 >> 3) & 1) * 2 + (((uint32_t)j & 15) >> 3)) * 4u
                               + (uint32_t)(j & 1) * 2u;
            *(unsigned short*)(smc + WAS_B + off) = __half_as_ushort(__float2half_rn(v));
        }
    }
    grid_barrier();

    // roles: phase A = 32 warps: 4 mi x 8 n-slots; tiles {2,1,1,1,1,1,1,2}
    const int mi = wid & 3;
    const int nslot = wid >> 2;
    const int nt0 = (nslot == 0) ? 0 : (nslot + 1);
    const int ntc = (nslot == 0 || nslot == 7) ? 2 : 1;
    const int g = lane >> 2, c4 = lane & 3;
    const int Bbg = bid >> 4, Bhg = bid & 15;

    for (int t = 0; t < T_DIM; t++) {
        // ================= PHASE A =================
        float d[2][4];
        #pragma unroll
        for (int tt = 0; tt < 2; tt++) { d[tt][0]=0.f; d[tt][1]=0.f; d[tt][2]=0.f; d[tt][3]=0.f; }

        copy_chunk(astg, g_hp, 2048, tid);
        __syncthreads();
        for (int c = 0; c <= 4; c++) {
            if (c < 4) {
                char* nbuf = astg + (((c + 1) & 1) ? 32768 : 0);
                if (c < 3) copy_chunk(nbuf, g_hp + (size_t)(c + 1) * 8192, 2048, tid);
                else       copy_chunk(nbuf, g_ep + (size_t)t * 4096, 1024, tid);
            }
            const char* bufp = astg + ((c & 1) ? 32768 : 0);
            const int nk = (c == 4) ? 4 : 8;
            for (int kl = 0; kl < nk; kl++) {
                const char* ap = bufp + (kl * 4 + mi) * 1024;
                const uint4 hv = *(const uint4*)(ap + ho);
                const uint4 lv = *(const uint4*)(ap + (ho ^ 16));
                const uint32_t ah[4] = {hv.x, hv.z, hv.y, hv.w};
                const uint32_t al[4] = {lv.x, lv.z, lv.y, lv.w};
                #pragma unroll
                for (int tt = 0; tt < 2; tt++) {
                    if (tt >= ntc) break;
                    const char* bp = (c == 4)
                        ? (smc + BEXT_B + (nt0 + tt) * 1024 + kl * 256)
                        : (smc + BF_B + (nt0 + tt) * 8192 + (c * 8 + kl) * 256);
                    const uint2 bv = *(const uint2*)(bp + lane * 8);
                    mma_h(d[tt], ah, bv.x, bv.y);
                    mma_h(d[tt], al, bv.x, bv.y);
                }
            }
            __syncthreads();
        }

        // epilogue: fast activations; fp32 l/f/o + packed fp16 l-frags
        #pragma unroll
        for (int tt = 0; tt < 2; tt++) {
            if (tt >= ntc) break;
            const int cl = (nt0 + tt) * 8 + c4 * 2;
            const int pq = bid * NPAIR + (cl >> 1);
            const int pt = pq >> 9, c = pq & 511;
            const float bA = bias_sm[cl], bB = bias_sm[cl + 1];
            const int b0 = mi * 16 + g, b1 = b0 + 8;
            const float sA0 = sig_fast(d[tt][0] + bA), sA1 = sig_fast(d[tt][2] + bA);
            if (pt == 1) {
                g_f[b0 * H_DIM + c] = sA0;
                g_f[b1 * H_DIM + c] = sA1;
                g_o[b0 * H_DIM + c] = sig_fast(d[tt][1] + bB);
                g_o[b1 * H_DIM + c] = sig_fast(d[tt][3] + bB);
            } else {
                const int kk = (pt == 0) ? 0 : pt - 1;
                const float lv0 = sA0 * tanh_fast(d[tt][1] + bB);
                const float lv1 = sA1 * tanh_fast(d[tt][3] + bB);
                g_l[((size_t)b0 * 9 + kk) * H_DIM + c] = lv0;
                g_l[((size_t)b1 * 9 + kk) * H_DIM + c] = lv1;
                const float n0 = __shfl_xor_sync(0xFFFFFFFFu, lv0, 1);
                const float n1 = __shfl_xor_sync(0xFFFFFFFFu, lv1, 1);
                const int ev = !(c4 & 1);
                const float pe0 = ev ? lv0 : n0, po0 = ev ? n0 : lv0;
                const float pe1 = ev ? lv1 : n1, po1 = ev ? n1 : lv1;
                const int cE = c & ~1;
                uint32_t hi0, lo0, hi1, lo1;
                cvt_pair_h(pe0, po0, hi0, lo0);
                cvt_pair_h(pe1, po1, hi1, lo1);
                const int lane2 = g * 4 + ((cE & 7) >> 1);
                const int slot = (kk & 1) * 2 + ((cE & 15) >> 3);
                const int mi2 = kk >> 1, j16 = cE >> 4;
                const int s = ev ? slot : (slot + 4);
                g_lp[((((size_t)(mi * 2) * 32 + j16) * 5 + mi2) * 32 + lane2) * 8 + s] = ev ? hi0 : lo0;
                g_lp[((((size_t)(mi * 2 + 1) * 32 + j16) * 5 + mi2) * 32 + lane2) * 8 + s] = ev ? hi1 : lo1;
            }
        }
        grid_barrier();

        // ================= PHASE B =================
        if (wid < 10) {
            float d2[2][4];
            #pragma unroll
            for (int n8 = 0; n8 < 2; n8++) { d2[n8][0]=0.f; d2[n8][1]=0.f; d2[n8][2]=0.f; d2[n8][3]=0.f; }
            const int mi2w = wid >> 1, n16 = wid & 1;
            #pragma unroll 4
            for (int kl = 0; kl < 32; kl++) {
                const uint4* ap = (const uint4*)(g_lp + ((((size_t)Bbg * 32 + kl) * 5 + mi2w) * 32 + lane) * 8);
                const uint4 hv = __ldg(ap), lv = __ldg(ap + 1);
                const uint32_t ah[4] = {hv.x, hv.z, hv.y, hv.w};
                const uint32_t al[4] = {lv.x, lv.z, lv.y, lv.w};
                const uint4 wv = *(const uint4*)(smc + WAS_B + kl * 1024 + n16 * 512 + lane * 16);
                mma_h(d2[0], ah, wv.x, wv.y);
                mma_h(d2[0], al, wv.x, wv.y);
                mma_h(d2[1], ah, wv.z, wv.w);
                mma_h(d2[1], al, wv.z, wv.w);
            }
            const int r0 = mi2w * 16 + g, r1 = r0 + 8;
            #pragma unroll
            for (int n8 = 0; n8 < 2; n8++) {
                const int n0 = n16 * 16 + n8 * 8 + c4 * 2;
                ub[r0 * 32 + n0]     = d2[n8][0];
                ub[r0 * 32 + n0 + 1] = d2[n8][1];
                if (r1 < 72) {
                    ub[r1 * 32 + n0]     = d2[n8][2];
                    ub[r1 * 32 + n0 + 1] = d2[n8][3];
                }
            }
        }
        __syncthreads();

        // combine + packed fp16 h store
        if (tid < 256) {
            const int bl2 = tid >> 5, hl2 = tid & 31;
            const int b = Bbg * 8 + bl2, h = Bhg * 32 + hl2;
            const float c_old = g_c[b * H_DIM + h];
            const float ba = p.b_a[h];
            float uu[9], mx = -1e30f;
            #pragma unroll
            for (int k = 0; k < 9; k++) {
                const float u = ub[(k * 8 + bl2) * 32 + hl2];
                uu[k] = tanh_fast(fmaf(u, c_old, ba));
                mx = fmaxf(mx, uu[k]);
            }
            float se = 0.0f, L = 0.0f;
            #pragma unroll
            for (int k = 0; k < 9; k++) {
                const float e = exp_fast(uu[k] - mx);
                se += e;
                L = fmaf(e, __ldcg(g_l + ((size_t)b * 9 + k) * H_DIM + h), L);
            }
            L /= se;
            const float cn = fmaf(__ldcg(g_f + b * H_DIM + h), c_old, L);
            const float hn = __ldcg(g_o + b * H_DIM + h) * tanh_fast(cn);
            g_c[b * H_DIM + h] = cn;

            const float nh = __shfl_xor_sync(0xFFFFFFFFu, hn, 1);
            const int ev = !(hl2 & 1);
            const float pe = ev ? hn : nh, po = ev ? nh : hn;
            uint32_t hi, lo;
            cvt_pair_h(pe, po, hi, lo);
            const int hE = h & ~1;
            const int lane2 = (b & 7) * 4 + ((hE & 7) >> 1);
            const int slot = ((b >> 3) & 1) * 2 + ((hE & 15) >> 3);
            const size_t dst = (((size_t)(hE >> 4) * 4 + (b >> 4)) * 32 + lane2) * 8;
            g_hp[dst + (ev ? slot : slot + 4)] = ev ? hi : lo;

            out[(size_t)seq_off + ((size_t)b * T_DIM + t) * H_DIM + h] = hn;
            if (write_hT && t == T_DIM - 1)
                out[(size_t)b * H_DIM + h] = hn;
        }
        grid_barrier();
    }
}

// ---------------------------------------------------------------------
extern "C" void kernel_launch(void* const* d_in, const int* in_sizes, int n_in,
                              void* d_out, int out_size)
{
    Params p;
    p.Y = (const float*)d_in[0];
    for (int j = 0; j < 8; j++) p.x[j] = (const float*)d_in[1 + j];
    const float* W_i = (const float*)d_in[9],  *U_i = (const float*)d_in[10], *b_i = (const float*)d_in[11];
    const float* W_f = (const float*)d_in[12], *U_f = (const float*)d_in[13], *b_f = (const float*)d_in[14];
    const float* W_c = (const float*)d_in[15], *U_c = (const float*)d_in[16], *b_c = (const float*)d_in[17];
    const float* W_o = (const float*)d_in[18], *U_o = (const float*)d_in[19], *b_o = (const float*)d_in[20];
    const float* W_i_x = (const float*)d_in[21], *U_i_x = (const float*)d_in[22], *b_i_x = (const float*)d_in[23];
    const float* W_c_x = (const float*)d_in[24], *U_c_x = (const float*)d_in[25], *b_c_x = (const float*)d_in[26];
    p.W_a = (const float*)d_in[27];
    p.b_a = (const float*)d_in[28];

    p.U[0] = U_i; p.U[1] = U_f; p.U[2] = U_c; p.U[3] = U_o;
    p.W[0] = W_i; p.W[1] = W_f; p.W[2] = W_c; p.W[3] = W_o;
    p.bb[0] = b_i; p.bb[1] = b_f; p.bb[2] = b_c; p.bb[3] = b_o;
    for (int k = 0; k < 8; k++) {
        p.U[4 + k]  = U_i_x + (size_t)k * H_DIM * H_DIM;
        p.U[12 + k] = U_c_x + (size_t)k * H_DIM * H_DIM;
        p.W[4 + k]  = W_i_x + (size_t)k * 3 * H_DIM;
        p.W[12 + k] = W_c_x + (size_t)k * 3 * H_DIM;
        p.bb[4 + k]  = b_i_x + (size_t)k * H_DIM;
        p.bb[12 + k] = b_c_x + (size_t)k * H_DIM;
    }

    float* out = (float*)d_out;
    const int full = B_DIM * H_DIM + B_DIM * T_DIM * H_DIM;
    const int seq_off = (out_size >= full) ? (B_DIM * H_DIM) : 0;
    const int write_hT = (seq_off != 0) ? 1 : 0;

    static int configured = 0;
    if (!configured) {
        cudaFuncSetAttribute(lstm_h4, cudaFuncAttributeMaxDynamicSharedMemorySize, SMEM_BYTES);
        configured = 1;
    }
    lstm_h4<<<GRID, BLK, SMEM_BYTES>>>(p, out, seq_off, write_hT);
}

// round 13
// speedup vs baseline: 1.1277x; 1.1277x over previous
#include <cuda_runtime.h>
#include <cuda_fp16.h>
#include <math.h>
#include <stdint.h>

#define B_DIM 64
#define T_DIM 1024
#define H_DIM 512
#define GRID  128
#define BLK   512
#define NPAIR 40

// ---- smem byte offsets ----
#define BF_B    0         // U-pair B-frags fp16: [nt10][kt32][lane32][8B] = 81920
#define BEXT_B  81920     // ext B-frags fp16: [nt10][ek4][lane32][8B] = 10240
#define WAS_B   92160     // W_a B-frags fp16: [kl32][n16 2][lane32][16B] = 32768
#define BIAS_B  124928    // 80 floats
#define UBUF_B  125248    // 72x32 fp32 = 9216
#define ASTG_B  134528    // A-stage double buffer 2x32KB
#define SMEM_BYTES 200064

// ---- device scratch ----
__device__ uint32_t g_hp[32 * 4 * 32 * 8];          // h A-frags fp16 split
__device__ uint32_t g_lp[8 * 32 * 5 * 32 * 8];      // l A-frags fp16 split
__device__ uint32_t g_ep[1024u * 4 * 4 * 32 * 8];   // ext A-frags fp16 split
__device__ float g_c[B_DIM * H_DIM];
__device__ float g_l[B_DIM * 9 * H_DIM];
__device__ float g_f[B_DIM * H_DIM];
__device__ float g_o[B_DIM * H_DIM];
// flag-array barrier state (one cache line per flag)
__device__ volatile unsigned g_flags[GRID * 32];
__device__ volatile unsigned g_release;

struct Params {
    const float* U[20];
    const float* W[20];
    const float* bb[20];
    const float* Y;
    const float* x[8];
    const float* W_a;
    const float* b_a;
};

// ---- fast activations (MUFU) ----
__device__ __forceinline__ float tanh_fast(float z) {
    float r; asm("tanh.approx.f32 %0, %1;" : "=f"(r) : "f"(z)); return r;
}
__device__ __forceinline__ float exp_fast(float z) {
    float r; asm("ex2.approx.ftz.f32 %0, %1;" : "=f"(r) : "f"(z * 1.4426950408889634f));
    return r;
}
__device__ __forceinline__ float sig_fast(float z) {
    float ex; asm("ex2.approx.ftz.f32 %0, %1;" : "=f"(ex) : "f"(z * -1.4426950408889634f));
    float r;  asm("rcp.approx.ftz.f32 %0, %1;" : "=f"(r) : "f"(1.0f + ex));
    return r;
}

__device__ __forceinline__ void cvt_pair_h(float v0, float v1, uint32_t& hi, uint32_t& lo)
{
    const __half h0 = __float2half_rn(v0), h1 = __float2half_rn(v1);
    const __half l0 = __float2half_rn(v0 - __half2float(h0));
    const __half l1 = __float2half_rn(v1 - __half2float(h1));
    hi = ((uint32_t)__half_as_ushort(h1) << 16) | __half_as_ushort(h0);
    lo = ((uint32_t)__half_as_ushort(l1) << 16) | __half_as_ushort(l0);
}

__device__ __forceinline__ void mma_h(float* d, const uint32_t* a, uint32_t b0, uint32_t b1)
{
    asm volatile(
        "mma.sync.aligned.m16n8k16.row.col.f32.f16.f16.f32 "
        "{%0,%1,%2,%3}, {%4,%5,%6,%7}, {%8,%9}, {%0,%1,%2,%3};"
        : "+f"(d[0]), "+f"(d[1]), "+f"(d[2]), "+f"(d[3])
        : "r"(a[0]), "r"(a[1]), "r"(a[2]), "r"(a[3]), "r"(b0), "r"(b1));
}

// flag-array grid barrier: no atomics, parallel gather by master CTA
__device__ __forceinline__ void grid_barrier(unsigned gen)
{
    __syncthreads();
    if (threadIdx.x == 0) {
        __threadfence();                 // make this CTA's writes visible first
        g_flags[blockIdx.x * 32] = gen;  // parallel arrival (distinct lines)
    }
    if (blockIdx.x == 0) {
        if (threadIdx.x < GRID) {
            while (g_flags[threadIdx.x * 32] < gen) { }
        }
        __syncthreads();
        if (threadIdx.x == 0) {
            __threadfence();
            g_release = gen;
        }
    }
    if (threadIdx.x == 0) {
        while (g_release < gen) { }
        __threadfence();                 // acquire: invalidate L1, see peers' data
    }
    __syncthreads();
}

__device__ __forceinline__ int memA(int pt) { return pt == 0 ? 0 : (pt == 1 ? 1 : pt + 2); }
__device__ __forceinline__ int memB(int pt) { return pt == 0 ? 2 : (pt == 1 ? 3 : pt + 10); }

extern __shared__ float sm[];

__device__ __forceinline__ void copy_chunk(char* dst, const uint32_t* src_u32, int n_uint4, int tid)
{
    const uint4* src = (const uint4*)src_u32;
    for (int i = tid; i < n_uint4; i += BLK) {
        const uint4 v = __ldg(src + i);
        const int half = i & 1, lane2 = (i >> 1) & 31, km = i >> 6;
        *(uint4*)(dst + km * 1024 + lane2 * 32 + ((half * 16) ^ ((lane2 & 4) << 2))) = v;
    }
}

__global__ __launch_bounds__(BLK, 1) void lstm_h5(Params p, float* __restrict__ out,
                                                  int seq_off, int write_hT)
{
    const int tid = threadIdx.x;
    const int bid = blockIdx.x;
    const int lane = tid & 31;
    const int wid = tid >> 5;
    const int gtid = bid * BLK + tid;
    char* smc = (char*)sm;
    float* bias_sm = (float*)(smc + BIAS_B);
    float* ub = (float*)(smc + UBUF_B);
    char* astg = smc + ASTG_B;
    const uint32_t ho = lane * 32 + ((lane & 4) << 2);
    unsigned gen = 0;

    for (int i = gtid; i < 32 * 4 * 32 * 8; i += GRID * BLK) g_hp[i] = 0u;
    for (int i = gtid; i < 8 * 32 * 5 * 32 * 8; i += GRID * BLK) g_lp[i] = 0u;
    for (int i = gtid; i < B_DIM * H_DIM; i += GRID * BLK) g_c[i] = 0.0f;

    // ---- one-time: ext input A-frags (all t) ----
    for (int idx = gtid; idx < T_DIM * 2048; idx += GRID * BLK) {
        const int t = idx >> 11;
        const int r = idx & 2047;
        const int b = r >> 5, q = (r & 31) * 2;
        float v0, v1;
        {
            const int qq = q;
            if (qq < 32) v0 = p.Y[((size_t)b * 32 + qq) * T_DIM + t];
            else if (qq < 56) { const int rr = qq - 32, xk = rr / 3, i2 = rr - 3 * xk;
                                v0 = p.x[xk][((size_t)b * 3 + i2) * T_DIM + t]; }
            else v0 = 0.0f;
        }
        {
            const int qq = q + 1;
            if (qq < 32) v1 = p.Y[((size_t)b * 32 + qq) * T_DIM + t];
            else if (qq < 56) { const int rr = qq - 32, xk = rr / 3, i2 = rr - 3 * xk;
                                v1 = p.x[xk][((size_t)b * 3 + i2) * T_DIM + t]; }
            else v1 = 0.0f;
        }
        uint32_t hi, lo; cvt_pair_h(v0, v1, hi, lo);
        const int lane2 = (b & 7) * 4 + ((q & 7) >> 1);
        const int slot = ((b >> 3) & 1) * 2 + ((q & 15) >> 3);
        const size_t base = ((((size_t)t * 4 + (q >> 4)) * 4 + (b >> 4)) * 32 + lane2) * 8 + slot;
        g_ep[base] = hi; g_ep[base + 4] = lo;
    }

    // ---- one-time: U pair-columns -> fp16 B-frags (smem) ----
    for (int e = tid; e < 80 * H_DIM; e += BLK) {
        const int s = e >> 9, j = e & 511;
        const int pq = bid * NPAIR + (s >> 1);
        const int pt = pq >> 9, c = pq & 511;
        const int m = (s & 1) ? memB(pt) : memA(pt);
        const float v = p.U[m][(size_t)j * H_DIM + c];
        const uint32_t off = (uint32_t)(s >> 3) * 8192u + (uint32_t)(j >> 4) * 256u
                           + (uint32_t)((s & 7) * 4 + ((j & 7) >> 1)) * 8u
                           + (uint32_t)((j & 15) >> 3) * 4u + (uint32_t)(j & 1) * 2u;
        *(unsigned short*)(smc + BF_B + off) = __half_as_ushort(__float2half_rn(v));
    }
    for (int e = tid; e < 2560; e += BLK) ((uint32_t*)(smc + BEXT_B))[e] = 0u;
    __syncthreads();
    for (int e = tid; e < 80 * 32; e += BLK) {
        const int s = e >> 5, i = e & 31;
        const int pq = bid * NPAIR + (s >> 1);
        const int pt = pq >> 9, c = pq & 511;
        const int m = (s & 1) ? memB(pt) : memA(pt);
        float v; int q;
        if (m < 4) { v = p.W[m][(size_t)i * H_DIM + c]; q = i; }
        else {
            if (i >= 3) continue;
            const int k = (m < 12) ? (m - 4) : (m - 12);
            const int xsel = (m < 12) ? ((k == 0) ? 0 : 1) : k;
            v = p.W[m][(size_t)i * H_DIM + c];
            q = 32 + xsel * 3 + i;
        }
        const uint32_t off = (uint32_t)(s >> 3) * 1024u + (uint32_t)(q >> 4) * 256u
                           + (uint32_t)((s & 7) * 4 + ((q & 7) >> 1)) * 8u
                           + (uint32_t)((q & 15) >> 3) * 4u + (uint32_t)(q & 1) * 2u;
        *(unsigned short*)(smc + BEXT_B + off) = __half_as_ushort(__float2half_rn(v));
    }
    for (int s = tid; s < 80; s += BLK) {
        const int pq = bid * NPAIR + (s >> 1);
        const int pt = pq >> 9, c = pq & 511;
        bias_sm[s] = p.bb[(s & 1) ? memB(pt) : memA(pt)][c];
    }
    {
        const int Bhg_ = bid & 15;
        for (int e = tid; e < 16384; e += BLK) {
            const int j = e >> 5, h2 = e & 31;
            const float v = p.W_a[(size_t)j * H_DIM + Bhg_ * 32 + h2];
            const uint32_t off = (uint32_t)(j >> 4) * 1024u + (uint32_t)(h2 >> 4) * 512u
                               + (uint32_t)((h2 & 7) * 4 + ((j & 7) >> 1)) * 16u
                               + ((((uint32_t)h2 >> 3) & 1) * 2 + (((uint32_t)j & 15) >> 3)) * 4u
                               + (uint32_t)(j & 1) * 2u;
            *(unsigned short*)(smc + WAS_B + off) = __half_as_ushort(__float2half_rn(v));
        }
    }
    grid_barrier(++gen);

    // roles (R11-best layout)
    const int mi = wid & 3;
    const int nslot = wid >> 2;
    const int nt0 = (nslot == 0) ? 0 : (nslot == 1) ? 3 : (nslot == 2) ? 5 : 8;
    const int ntc = (nslot == 1 || nslot == 3) ? 2 : 3;
    const int g = lane >> 2, c4 = lane & 3;
    const int Bbg = bid >> 4, Bhg = bid & 15;

    for (int t = 0; t < T_DIM; t++) {
        // ================= PHASE A =================
        float d[3][4];
        #pragma unroll
        for (int tt = 0; tt < 3; tt++) { d[tt][0]=0.f; d[tt][1]=0.f; d[tt][2]=0.f; d[tt][3]=0.f; }

        copy_chunk(astg, g_hp, 2048, tid);
        __syncthreads();
        for (int c = 0; c <= 4; c++) {
            if (c < 4) {
                char* nbuf = astg + (((c + 1) & 1) ? 32768 : 0);
                if (c < 3) copy_chunk(nbuf, g_hp + (size_t)(c + 1) * 8192, 2048, tid);
                else       copy_chunk(nbuf, g_ep + (size_t)t * 4096, 1024, tid);
            }
            const char* bufp = astg + ((c & 1) ? 32768 : 0);
            const int nk = (c == 4) ? 4 : 8;
            for (int kl = 0; kl < nk; kl++) {
                const char* ap = bufp + (kl * 4 + mi) * 1024;
                const uint4 hv = *(const uint4*)(ap + ho);
                const uint4 lv = *(const uint4*)(ap + (ho ^ 16));
                const uint32_t ah[4] = {hv.x, hv.z, hv.y, hv.w};
                const uint32_t al[4] = {lv.x, lv.z, lv.y, lv.w};
                #pragma unroll
                for (int tt = 0; tt < 3; tt++) {
                    if (tt >= ntc) break;
                    const char* bp = (c == 4)
                        ? (smc + BEXT_B + (nt0 + tt) * 1024 + kl * 256)
                        : (smc + BF_B + (nt0 + tt) * 8192 + (c * 8 + kl) * 256);
                    const uint2 bv = *(const uint2*)(bp + lane * 8);
                    mma_h(d[tt], ah, bv.x, bv.y);
                    mma_h(d[tt], al, bv.x, bv.y);
                }
            }
            __syncthreads();
        }

        // epilogue
        #pragma unroll
        for (int tt = 0; tt < 3; tt++) {
            if (tt >= ntc) break;
            const int cl = (nt0 + tt) * 8 + c4 * 2;
            const int pq = bid * NPAIR + (cl >> 1);
            const int pt = pq >> 9, c = pq & 511;
            const float bA = bias_sm[cl], bB = bias_sm[cl + 1];
            const int b0 = mi * 16 + g, b1 = b0 + 8;
            const float sA0 = sig_fast(d[tt][0] + bA), sA1 = sig_fast(d[tt][2] + bA);
            if (pt == 1) {
                g_f[b0 * H_DIM + c] = sA0;
                g_f[b1 * H_DIM + c] = sA1;
                g_o[b0 * H_DIM + c] = sig_fast(d[tt][1] + bB);
                g_o[b1 * H_DIM + c] = sig_fast(d[tt][3] + bB);
            } else {
                const int kk = (pt == 0) ? 0 : pt - 1;
                const float lv0 = sA0 * tanh_fast(d[tt][1] + bB);
                const float lv1 = sA1 * tanh_fast(d[tt][3] + bB);
                g_l[((size_t)b0 * 9 + kk) * H_DIM + c] = lv0;
                g_l[((size_t)b1 * 9 + kk) * H_DIM + c] = lv1;
                const float n0 = __shfl_xor_sync(0xFFFFFFFFu, lv0, 1);
                const float n1 = __shfl_xor_sync(0xFFFFFFFFu, lv1, 1);
                const int ev = !(c4 & 1);
                const float pe0 = ev ? lv0 : n0, po0 = ev ? n0 : lv0;
                const float pe1 = ev ? lv1 : n1, po1 = ev ? n1 : lv1;
                const int cE = c & ~1;
                uint32_t hi0, lo0, hi1, lo1;
                cvt_pair_h(pe0, po0, hi0, lo0);
                cvt_pair_h(pe1, po1, hi1, lo1);
                const int lane2 = g * 4 + ((cE & 7) >> 1);
                const int slot = (kk & 1) * 2 + ((cE & 15) >> 3);
                const int mi2 = kk >> 1, j16 = cE >> 4;
                const int s = ev ? slot : (slot + 4);
                g_lp[((((size_t)(mi * 2) * 32 + j16) * 5 + mi2) * 32 + lane2) * 8 + s] = ev ? hi0 : lo0;
                g_lp[((((size_t)(mi * 2 + 1) * 32 + j16) * 5 + mi2) * 32 + lane2) * 8 + s] = ev ? hi1 : lo1;
            }
        }
        grid_barrier(++gen);

        // ================= PHASE B =================
        if (wid < 10) {
            float d2[2][4];
            #pragma unroll
            for (int n8 = 0; n8 < 2; n8++) { d2[n8][0]=0.f; d2[n8][1]=0.f; d2[n8][2]=0.f; d2[n8][3]=0.f; }
            const int mi2w = wid >> 1, n16 = wid & 1;
            #pragma unroll 4
            for (int kl = 0; kl < 32; kl++) {
                const uint4* ap = (const uint4*)(g_lp + ((((size_t)Bbg * 32 + kl) * 5 + mi2w) * 32 + lane) * 8);
                const uint4 hv = __ldg(ap), lv = __ldg(ap + 1);
                const uint32_t ah[4] = {hv.x, hv.z, hv.y, hv.w};
                const uint32_t al[4] = {lv.x, lv.z, lv.y, lv.w};
                const uint4 wv = *(const uint4*)(smc + WAS_B + kl * 1024 + n16 * 512 + lane * 16);
                mma_h(d2[0], ah, wv.x, wv.y);
                mma_h(d2[0], al, wv.x, wv.y);
                mma_h(d2[1], ah, wv.z, wv.w);
                mma_h(d2[1], al, wv.z, wv.w);
            }
            const int r0 = mi2w * 16 + g, r1 = r0 + 8;
            #pragma unroll
            for (int n8 = 0; n8 < 2; n8++) {
                const int n0 = n16 * 16 + n8 * 8 + c4 * 2;
                ub[r0 * 32 + n0]     = d2[n8][0];
                ub[r0 * 32 + n0 + 1] = d2[n8][1];
                if (r1 < 72) {
                    ub[r1 * 32 + n0]     = d2[n8][2];
                    ub[r1 * 32 + n0 + 1] = d2[n8][3];
                }
            }
        }
        __syncthreads();

        // combine + packed fp16 h store
        if (tid < 256) {
            const int bl2 = tid >> 5, hl2 = tid & 31;
            const int b = Bbg * 8 + bl2, h = Bhg * 32 + hl2;
            const float c_old = g_c[b * H_DIM + h];
            const float ba = p.b_a[h];
            float uu[9], mx = -1e30f;
            #pragma unroll
            for (int k = 0; k < 9; k++) {
                const float u = ub[(k * 8 + bl2) * 32 + hl2];
                uu[k] = tanh_fast(fmaf(u, c_old, ba));
                mx = fmaxf(mx, uu[k]);
            }
            float se = 0.0f, L = 0.0f;
            #pragma unroll
            for (int k = 0; k < 9; k++) {
                const float e = exp_fast(uu[k] - mx);
                se += e;
                L = fmaf(e, __ldcg(g_l + ((size_t)b * 9 + k) * H_DIM + h), L);
            }
            L /= se;
            const float cn = fmaf(__ldcg(g_f + b * H_DIM + h), c_old, L);
            const float hn = __ldcg(g_o + b * H_DIM + h) * tanh_fast(cn);
            g_c[b * H_DIM + h] = cn;

            const float nh = __shfl_xor_sync(0xFFFFFFFFu, hn, 1);
            const int ev = !(hl2 & 1);
            const float pe = ev ? hn : nh, po = ev ? nh : hn;
            uint32_t hi, lo;
            cvt_pair_h(pe, po, hi, lo);
            const int hE = h & ~1;
            const int lane2 = (b & 7) * 4 + ((hE & 7) >> 1);
            const int slot = ((b >> 3) & 1) * 2 + ((hE & 15) >> 3);
            const size_t dst = (((size_t)(hE >> 4) * 4 + (b >> 4)) * 32 + lane2) * 8;
            g_hp[dst + (ev ? slot : slot + 4)] = ev ? hi : lo;

            out[(size_t)seq_off + ((size_t)b * T_DIM + t) * H_DIM + h] = hn;
            if (write_hT && t == T_DIM - 1)
                out[(size_t)b * H_DIM + h] = hn;
        }
        grid_barrier(++gen);
    }
}

// ---------------------------------------------------------------------
extern "C" void kernel_launch(void* const* d_in, const int* in_sizes, int n_in,
                              void* d_out, int out_size)
{
    Params p;
    p.Y = (const float*)d_in[0];
    for (int j = 0; j < 8; j++) p.x[j] = (const float*)d_in[1 + j];
    const float* W_i = (const float*)d_in[9],  *U_i = (const float*)d_in[10], *b_i = (const float*)d_in[11];
    const float* W_f = (const float*)d_in[12], *U_f = (const float*)d_in[13], *b_f = (const float*)d_in[14];
    const float* W_c = (const float*)d_in[15], *U_c = (const float*)d_in[16], *b_c = (const float*)d_in[17];
    const float* W_o = (const float*)d_in[18], *U_o = (const float*)d_in[19], *b_o = (const float*)d_in[20];
    const float* W_i_x = (const float*)d_in[21], *U_i_x = (const float*)d_in[22], *b_i_x = (const float*)d_in[23];
    const float* W_c_x = (const float*)d_in[24], *U_c_x = (const float*)d_in[25], *b_c_x = (const float*)d_in[26];
    p.W_a = (const float*)d_in[27];
    p.b_a = (const float*)d_in[28];

    p.U[0] = U_i; p.U[1] = U_f; p.U[2] = U_c; p.U[3] = U_o;
    p.W[0] = W_i; p.W[1] = W_f; p.W[2] = W_c; p.W[3] = W_o;
    p.bb[0] = b_i; p.bb[1] = b_f; p.bb[2] = b_c; p.bb[3] = b_o;
    for (int k = 0; k < 8; k++) {
        p.U[4 + k]  = U_i_x + (size_t)k * H_DIM * H_DIM;
        p.U[12 + k] = U_c_x + (size_t)k * H_DIM * H_DIM;
        p.W[4 + k]  = W_i_x + (size_t)k * 3 * H_DIM;
        p.W[12 + k] = W_c_x + (size_t)k * 3 * H_DIM;
        p.bb[4 + k]  = b_i_x + (size_t)k * H_DIM;
        p.bb[12 + k] = b_c_x + (size_t)k * H_DIM;
    }

    float* out = (float*)d_out;
    const int full = B_DIM * H_DIM + B_DIM * T_DIM * H_DIM;
    const int seq_off = (out_size >= full) ? (B_DIM * H_DIM) : 0;
    const int write_hT = (seq_off != 0) ? 1 : 0;

    static int configured = 0;
    if (!configured) {
        cudaFuncSetAttribute(lstm_h5, cudaFuncAttributeMaxDynamicSharedMemorySize, SMEM_BYTES);
        configured = 1;
    }
    lstm_h5<<<GRID, BLK, SMEM_BYTES>>>(p, out, seq_off, write_hT);
}

// round 14
// speedup vs baseline: 1.5288x; 1.3557x over previous
#include <cuda_runtime.h>
#include <cuda_fp16.h>
#include <math.h>
#include <stdint.h>

#define B_DIM 64
#define T_DIM 1024
#define H_DIM 512
#define GRID  128
#define BLK   512
#define NPAIR 40

// ---- smem byte offsets ----
#define BF_B    0         // U-pair B-frags fp16: [nt10][kt32][lane32][8B] = 81920
#define BEXT_B  81920     // ext B-frags fp16: [nt10][ek4][lane32][8B] = 10240
#define WAS_B   92160     // W_a B-frags fp16: [kl32][n16 2][lane32][16B] = 32768
#define BIAS_B  124928    // 80 floats
#define UBUF_B  125248    // 72x32 fp32 = 9216
#define SMEM_BYTES 134528

// ---- device scratch ----
__device__ uint32_t g_hp[32 * 4 * 32 * 8];          // h A-frags fp16 split [kt][mi][lane][4hi,4lo]
__device__ uint32_t g_lp[8 * 32 * 5 * 32 * 8];      // l A-frags fp16 split [Bbg][kl][mi2][lane][8]
__device__ uint32_t g_ep[1024u * 4 * 4 * 32 * 8];   // ext A-frags fp16 split [t][ek][mi][lane][8]
__device__ float g_c[B_DIM * H_DIM];
__device__ float g_l[B_DIM * 9 * H_DIM];
__device__ float g_f[B_DIM * H_DIM];
__device__ float g_o[B_DIM * H_DIM];
__device__ unsigned g_bar_count = 0;
__device__ volatile unsigned g_bar_gen = 0;

struct Params {
    const float* U[20];
    const float* W[20];
    const float* bb[20];
    const float* Y;
    const float* x[8];
    const float* W_a;
    const float* b_a;
};

// ---- fast activations (MUFU) ----
__device__ __forceinline__ float tanh_fast(float z) {
    float r; asm("tanh.approx.f32 %0, %1;" : "=f"(r) : "f"(z)); return r;
}
__device__ __forceinline__ float exp_fast(float z) {
    float r; asm("ex2.approx.ftz.f32 %0, %1;" : "=f"(r) : "f"(z * 1.4426950408889634f));
    return r;
}
__device__ __forceinline__ float sig_fast(float z) {
    float ex; asm("ex2.approx.ftz.f32 %0, %1;" : "=f"(ex) : "f"(z * -1.4426950408889634f));
    float r;  asm("rcp.approx.ftz.f32 %0, %1;" : "=f"(r) : "f"(1.0f + ex));
    return r;
}

__device__ __forceinline__ void cvt_pair_h(float v0, float v1, uint32_t& hi, uint32_t& lo)
{
    const __half h0 = __float2half_rn(v0), h1 = __float2half_rn(v1);
    const __half l0 = __float2half_rn(v0 - __half2float(h0));
    const __half l1 = __float2half_rn(v1 - __half2float(h1));
    hi = ((uint32_t)__half_as_ushort(h1) << 16) | __half_as_ushort(h0);
    lo = ((uint32_t)__half_as_ushort(l1) << 16) | __half_as_ushort(l0);
}

__device__ __forceinline__ void mma_h(float* d, const uint32_t* a, uint32_t b0, uint32_t b1)
{
    asm volatile(
        "mma.sync.aligned.m16n8k16.row.col.f32.f16.f16.f32 "
        "{%0,%1,%2,%3}, {%4,%5,%6,%7}, {%8,%9}, {%0,%1,%2,%3};"
        : "+f"(d[0]), "+f"(d[1]), "+f"(d[2]), "+f"(d[3])
        : "r"(a[0]), "r"(a[1]), "r"(a[2]), "r"(a[3]), "r"(b0), "r"(b1));
}

// counting barrier with nanosleep backoff (empirically best variant)
__device__ __forceinline__ void grid_barrier()
{
    __syncthreads();
    if (threadIdx.x == 0) {
        __threadfence();
        unsigned gen = g_bar_gen;
        if (atomicAdd(&g_bar_count, 1u) == (unsigned)(gridDim.x - 1)) {
            g_bar_count = 0;
            __threadfence();
            g_bar_gen = gen + 1;
        } else {
            while (g_bar_gen == gen) { __nanosleep(32); }
            __threadfence();
        }
    }
    __syncthreads();
}

__device__ __forceinline__ int memA(int pt) { return pt == 0 ? 0 : (pt == 1 ? 1 : pt + 2); }
__device__ __forceinline__ int memB(int pt) { return pt == 0 ? 2 : (pt == 1 ? 3 : pt + 10); }

extern __shared__ float sm[];

__global__ __launch_bounds__(BLK, 1) void lstm_h6(Params p, float* __restrict__ out,
                                                  int seq_off, int write_hT)
{
    const int tid = threadIdx.x;
    const int bid = blockIdx.x;
    const int lane = tid & 31;
    const int wid = tid >> 5;
    const int gtid = bid * BLK + tid;
    char* smc = (char*)sm;
    float* bias_sm = (float*)(smc + BIAS_B);
    float* ub = (float*)(smc + UBUF_B);

    for (int i = gtid; i < 32 * 4 * 32 * 8; i += GRID * BLK) g_hp[i] = 0u;
    for (int i = gtid; i < 8 * 32 * 5 * 32 * 8; i += GRID * BLK) g_lp[i] = 0u;
    for (int i = gtid; i < B_DIM * H_DIM; i += GRID * BLK) g_c[i] = 0.0f;

    // ---- one-time: ext input A-frags (all t) ----
    for (int idx = gtid; idx < T_DIM * 2048; idx += GRID * BLK) {
        const int t = idx >> 11;
        const int r = idx & 2047;
        const int b = r >> 5, q = (r & 31) * 2;
        float v0, v1;
        {
            const int qq = q;
            if (qq < 32) v0 = p.Y[((size_t)b * 32 + qq) * T_DIM + t];
            else if (qq < 56) { const int rr = qq - 32, xk = rr / 3, i2 = rr - 3 * xk;
                                v0 = p.x[xk][((size_t)b * 3 + i2) * T_DIM + t]; }
            else v0 = 0.0f;
        }
        {
            const int qq = q + 1;
            if (qq < 32) v1 = p.Y[((size_t)b * 32 + qq) * T_DIM + t];
            else if (qq < 56) { const int rr = qq - 32, xk = rr / 3, i2 = rr - 3 * xk;
                                v1 = p.x[xk][((size_t)b * 3 + i2) * T_DIM + t]; }
            else v1 = 0.0f;
        }
        uint32_t hi, lo; cvt_pair_h(v0, v1, hi, lo);
        const int lane2 = (b & 7) * 4 + ((q & 7) >> 1);
        const int slot = ((b >> 3) & 1) * 2 + ((q & 15) >> 3);
        const size_t base = ((((size_t)t * 4 + (q >> 4)) * 4 + (b >> 4)) * 32 + lane2) * 8 + slot;
        g_ep[base] = hi; g_ep[base + 4] = lo;
    }

    // ---- one-time: U pair-columns -> fp16 B-frags (smem) ----
    for (int e = tid; e < 80 * H_DIM; e += BLK) {
        const int s = e >> 9, j = e & 511;
        const int pq = bid * NPAIR + (s >> 1);
        const int pt = pq >> 9, c = pq & 511;
        const int m = (s & 1) ? memB(pt) : memA(pt);
        const float v = p.U[m][(size_t)j * H_DIM + c];
        const uint32_t off = (uint32_t)(s >> 3) * 8192u + (uint32_t)(j >> 4) * 256u
                           + (uint32_t)((s & 7) * 4 + ((j & 7) >> 1)) * 8u
                           + (uint32_t)((j & 15) >> 3) * 4u + (uint32_t)(j & 1) * 2u;
        *(unsigned short*)(smc + BF_B + off) = __half_as_ushort(__float2half_rn(v));
    }
    for (int e = tid; e < 2560; e += BLK) ((uint32_t*)(smc + BEXT_B))[e] = 0u;
    __syncthreads();
    for (int e = tid; e < 80 * 32; e += BLK) {
        const int s = e >> 5, i = e & 31;
        const int pq = bid * NPAIR + (s >> 1);
        const int pt = pq >> 9, c = pq & 511;
        const int m = (s & 1) ? memB(pt) : memA(pt);
        float v; int q;
        if (m < 4) { v = p.W[m][(size_t)i * H_DIM + c]; q = i; }
        else {
            if (i >= 3) continue;
            const int k = (m < 12) ? (m - 4) : (m - 12);
            const int xsel = (m < 12) ? ((k == 0) ? 0 : 1) : k;
            v = p.W[m][(size_t)i * H_DIM + c];
            q = 32 + xsel * 3 + i;
        }
        const uint32_t off = (uint32_t)(s >> 3) * 1024u + (uint32_t)(q >> 4) * 256u
                           + (uint32_t)((s & 7) * 4 + ((q & 7) >> 1)) * 8u
                           + (uint32_t)((q & 15) >> 3) * 4u + (uint32_t)(q & 1) * 2u;
        *(unsigned short*)(smc + BEXT_B + off) = __half_as_ushort(__float2half_rn(v));
    }
    for (int s = tid; s < 80; s += BLK) {
        const int pq = bid * NPAIR + (s >> 1);
        const int pt = pq >> 9, c = pq & 511;
        bias_sm[s] = p.bb[(s & 1) ? memB(pt) : memA(pt)][c];
    }
    {
        const int Bhg_ = bid & 15;
        for (int e = tid; e < 16384; e += BLK) {
            const int j = e >> 5, h2 = e & 31;
            const float v = p.W_a[(size_t)j * H_DIM + Bhg_ * 32 + h2];
            const uint32_t off = (uint32_t)(j >> 4) * 1024u + (uint32_t)(h2 >> 4) * 512u
                               + (uint32_t)((h2 & 7) * 4 + ((j & 7) >> 1)) * 16u
                               + ((((uint32_t)h2 >> 3) & 1) * 2 + (((uint32_t)j & 15) >> 3)) * 4u
                               + (uint32_t)(j & 1) * 2u;
            *(unsigned short*)(smc + WAS_B + off) = __half_as_ushort(__float2half_rn(v));
        }
    }
    grid_barrier();

    // roles (R11 layout)
    const int mi = wid & 3;
    const int nslot = wid >> 2;
    const int nt0 = (nslot == 0) ? 0 : (nslot == 1) ? 3 : (nslot == 2) ? 5 : 8;
    const int ntc = (nslot == 1 || nslot == 3) ? 2 : 3;
    const int g = lane >> 2, c4 = lane & 3;
    const int Bbg = bid >> 4, Bhg = bid & 15;

    for (int t = 0; t < T_DIM; t++) {
        // ================= PHASE A: sync-free, direct LDG A-frags =================
        float d[3][4];
        #pragma unroll
        for (int tt = 0; tt < 3; tt++) { d[tt][0]=0.f; d[tt][1]=0.f; d[tt][2]=0.f; d[tt][3]=0.f; }

        #pragma unroll 4
        for (int kt = 0; kt < 32; kt++) {
            const uint4* ap = (const uint4*)(g_hp + (((size_t)kt * 4 + mi) * 32 + lane) * 8);
            const uint4 hv = __ldg(ap), lv = __ldg(ap + 1);
            const uint32_t ah[4] = {hv.x, hv.z, hv.y, hv.w};
            const uint32_t al[4] = {lv.x, lv.z, lv.y, lv.w};
            #pragma unroll
            for (int tt = 0; tt < 3; tt++) {
                if (tt >= ntc) break;
                const uint2 bv = *(const uint2*)(smc + BF_B + (nt0 + tt) * 8192 + kt * 256 + lane * 8);
                mma_h(d[tt], ah, bv.x, bv.y);
                mma_h(d[tt], al, bv.x, bv.y);
            }
        }
        #pragma unroll
        for (int ek = 0; ek < 4; ek++) {
            const uint4* ap = (const uint4*)(g_ep + ((((size_t)t * 4 + ek) * 4 + mi) * 32 + lane) * 8);
            const uint4 hv = __ldg(ap), lv = __ldg(ap + 1);
            const uint32_t ah[4] = {hv.x, hv.z, hv.y, hv.w};
            const uint32_t al[4] = {lv.x, lv.z, lv.y, lv.w};
            #pragma unroll
            for (int tt = 0; tt < 3; tt++) {
                if (tt >= ntc) break;
                const uint2 bv = *(const uint2*)(smc + BEXT_B + (nt0 + tt) * 1024 + ek * 256 + lane * 8);
                mma_h(d[tt], ah, bv.x, bv.y);
                mma_h(d[tt], al, bv.x, bv.y);
            }
        }

        // epilogue
        #pragma unroll
        for (int tt = 0; tt < 3; tt++) {
            if (tt >= ntc) break;
            const int cl = (nt0 + tt) * 8 + c4 * 2;
            const int pq = bid * NPAIR + (cl >> 1);
            const int pt = pq >> 9, c = pq & 511;
            const float bA = bias_sm[cl], bB = bias_sm[cl + 1];
            const int b0 = mi * 16 + g, b1 = b0 + 8;
            const float sA0 = sig_fast(d[tt][0] + bA), sA1 = sig_fast(d[tt][2] + bA);
            if (pt == 1) {
                g_f[b0 * H_DIM + c] = sA0;
                g_f[b1 * H_DIM + c] = sA1;
                g_o[b0 * H_DIM + c] = sig_fast(d[tt][1] + bB);
                g_o[b1 * H_DIM + c] = sig_fast(d[tt][3] + bB);
            } else {
                const int kk = (pt == 0) ? 0 : pt - 1;
                const float lv0 = sA0 * tanh_fast(d[tt][1] + bB);
                const float lv1 = sA1 * tanh_fast(d[tt][3] + bB);
                g_l[((size_t)b0 * 9 + kk) * H_DIM + c] = lv0;
                g_l[((size_t)b1 * 9 + kk) * H_DIM + c] = lv1;
                const float n0 = __shfl_xor_sync(0xFFFFFFFFu, lv0, 1);
                const float n1 = __shfl_xor_sync(0xFFFFFFFFu, lv1, 1);
                const int ev = !(c4 & 1);
                const float pe0 = ev ? lv0 : n0, po0 = ev ? n0 : lv0;
                const float pe1 = ev ? lv1 : n1, po1 = ev ? n1 : lv1;
                const int cE = c & ~1;
                uint32_t hi0, lo0, hi1, lo1;
                cvt_pair_h(pe0, po0, hi0, lo0);
                cvt_pair_h(pe1, po1, hi1, lo1);
                const int lane2 = g * 4 + ((cE & 7) >> 1);
                const int slot = (kk & 1) * 2 + ((cE & 15) >> 3);
                const int mi2 = kk >> 1, j16 = cE >> 4;
                const int s = ev ? slot : (slot + 4);
                g_lp[((((size_t)(mi * 2) * 32 + j16) * 5 + mi2) * 32 + lane2) * 8 + s] = ev ? hi0 : lo0;
                g_lp[((((size_t)(mi * 2 + 1) * 32 + j16) * 5 + mi2) * 32 + lane2) * 8 + s] = ev ? hi1 : lo1;
            }
        }
        grid_barrier();

        // ================= PHASE B: LDG(A) + smem(Wa), deep unroll =================
        if (wid < 10) {
            float d2[2][4];
            #pragma unroll
            for (int n8 = 0; n8 < 2; n8++) { d2[n8][0]=0.f; d2[n8][1]=0.f; d2[n8][2]=0.f; d2[n8][3]=0.f; }
            const int mi2w = wid >> 1, n16 = wid & 1;
            #pragma unroll 8
            for (int kl = 0; kl < 32; kl++) {
                const uint4* ap = (const uint4*)(g_lp + ((((size_t)Bbg * 32 + kl) * 5 + mi2w) * 32 + lane) * 8);
                const uint4 hv = __ldg(ap), lv = __ldg(ap + 1);
                const uint32_t ah[4] = {hv.x, hv.z, hv.y, hv.w};
                const uint32_t al[4] = {lv.x, lv.z, lv.y, lv.w};
                const uint4 wv = *(const uint4*)(smc + WAS_B + kl * 1024 + n16 * 512 + lane * 16);
                mma_h(d2[0], ah, wv.x, wv.y);
                mma_h(d2[0], al, wv.x, wv.y);
                mma_h(d2[1], ah, wv.z, wv.w);
                mma_h(d2[1], al, wv.z, wv.w);
            }
            const int r0 = mi2w * 16 + g, r1 = r0 + 8;
            #pragma unroll
            for (int n8 = 0; n8 < 2; n8++) {
                const int n0 = n16 * 16 + n8 * 8 + c4 * 2;
                ub[r0 * 32 + n0]     = d2[n8][0];
                ub[r0 * 32 + n0 + 1] = d2[n8][1];
                if (r1 < 72) {
                    ub[r1 * 32 + n0]     = d2[n8][2];
                    ub[r1 * 32 + n0 + 1] = d2[n8][3];
                }
            }
        }
        __syncthreads();

        // combine + packed fp16 h store
        if (tid < 256) {
            const int bl2 = tid >> 5, hl2 = tid & 31;
            const int b = Bbg * 8 + bl2, h = Bhg * 32 + hl2;
            const float c_old = g_c[b * H_DIM + h];
            const float ba = p.b_a[h];
            float uu[9], mx = -1e30f;
            #pragma unroll
            for (int k = 0; k < 9; k++) {
                const float u = ub[(k * 8 + bl2) * 32 + hl2];
                uu[k] = tanh_fast(fmaf(u, c_old, ba));
                mx = fmaxf(mx, uu[k]);
            }
            float se = 0.0f, L = 0.0f;
            #pragma unroll
            for (int k = 0; k < 9; k++) {
                const float e = exp_fast(uu[k] - mx);
                se += e;
                L = fmaf(e, __ldcg(g_l + ((size_t)b * 9 + k) * H_DIM + h), L);
            }
            L /= se;
            const float cn = fmaf(__ldcg(g_f + b * H_DIM + h), c_old, L);
            const float hn = __ldcg(g_o + b * H_DIM + h) * tanh_fast(cn);
            g_c[b * H_DIM + h] = cn;

            const float nh = __shfl_xor_sync(0xFFFFFFFFu, hn, 1);
            const int ev = !(hl2 & 1);
            const float pe = ev ? hn : nh, po = ev ? nh : hn;
            uint32_t hi, lo;
            cvt_pair_h(pe, po, hi, lo);
            const int hE = h & ~1;
            const int lane2 = (b & 7) * 4 + ((hE & 7) >> 1);
            const int slot = ((b >> 3) & 1) * 2 + ((hE & 15) >> 3);
            const size_t dst = (((size_t)(hE >> 4) * 4 + (b >> 4)) * 32 + lane2) * 8;
            g_hp[dst + (ev ? slot : slot + 4)] = ev ? hi : lo;

            out[(size_t)seq_off + ((size_t)b * T_DIM + t) * H_DIM + h] = hn;
            if (write_hT && t == T_DIM - 1)
                out[(size_t)b * H_DIM + h] = hn;
        }
        grid_barrier();
    }
}

// ---------------------------------------------------------------------
extern "C" void kernel_launch(void* const* d_in, const int* in_sizes, int n_in,
                              void* d_out, int out_size)
{
    Params p;
    p.Y = (const float*)d_in[0];
    for (int j = 0; j < 8; j++) p.x[j] = (const float*)d_in[1 + j];
    const float* W_i = (const float*)d_in[9],  *U_i = (const float*)d_in[10], *b_i = (const float*)d_in[11];
    const float* W_f = (const float*)d_in[12], *U_f = (const float*)d_in[13], *b_f = (const float*)d_in[14];
    const float* W_c = (const float*)d_in[15], *U_c = (const float*)d_in[16], *b_c = (const float*)d_in[17];
    const float* W_o = (const float*)d_in[18], *U_o = (const float*)d_in[19], *b_o = (const float*)d_in[20];
    const float* W_i_x = (const float*)d_in[21], *U_i_x = (const float*)d_in[22], *b_i_x = (const float*)d_in[23];
    const float* W_c_x = (const float*)d_in[24], *U_c_x = (const float*)d_in[25], *b_c_x = (const float*)d_in[26];
    p.W_a = (const float*)d_in[27];
    p.b_a = (const float*)d_in[28];

    p.U[0] = U_i; p.U[1] = U_f; p.U[2] = U_c; p.U[3] = U_o;
    p.W[0] = W_i; p.W[1] = W_f; p.W[2] = W_c; p.W[3] = W_o;
    p.bb[0] = b_i; p.bb[1] = b_f; p.bb[2] = b_c; p.bb[3] = b_o;
    for (int k = 0; k < 8; k++) {
        p.U[4 + k]  = U_i_x + (size_t)k * H_DIM * H_DIM;
        p.U[12 + k] = U_c_x + (size_t)k * H_DIM * H_DIM;
        p.W[4 + k]  = W_i_x + (size_t)k * 3 * H_DIM;
        p.W[12 + k] = W_c_x + (size_t)k * 3 * H_DIM;
        p.bb[4 + k]  = b_i_x + (size_t)k * H_DIM;
        p.bb[12 + k] = b_c_x + (size_t)k * H_DIM;
    }

    float* out = (float*)d_out;
    const int full = B_DIM * H_DIM + B_DIM * T_DIM * H_DIM;
    const int seq_off = (out_size >= full) ? (B_DIM * H_DIM) : 0;
    const int write_hT = (seq_off != 0) ? 1 : 0;

    static int configured = 0;
    if (!configured) {
        cudaFuncSetAttribute(lstm_h6, cudaFuncAttributeMaxDynamicSharedMemorySize, SMEM_BYTES);
        configured = 1;
    }
    lstm_h6<<<GRID, BLK, SMEM_BYTES>>>(p, out, seq_off, write_hT);
}

// round 15
// speedup vs baseline: 2.2800x; 1.4914x over previous
#include <cuda_runtime.h>
#include <cuda_fp16.h>
#include <math.h>
#include <stdint.h>

#define B_DIM 64
#define T_DIM 1024
#define H_DIM 512
#define GRID  128
#define BLK   512
#define NPAIR 40

// ---- smem byte offsets ----
#define BF_B    0         // U-pair B-frags fp16: [nt10][kt32][lane32][8B] = 81920
#define BEXT_B  81920     // ext B-frags fp16: [nt10][ek4][lane32][8B] = 10240
#define WAS_B   92160     // W_a B-frags fp16: [kl32][n16 2][lane32][16B] = 32768
#define BIAS_B  124928    // 80 floats
#define UBUF_B  125248    // 72x32 fp32 = 9216
#define EXTS_B  134528    // staged ext A-frags for next t: 512 x 16B = 8192
#define SMEM_BYTES 142720

// ---- device scratch (single-product fp16 A-frags: 4 u32 per lane entry) ----
__device__ uint32_t g_hp[32 * 4 * 32 * 4];          // h A-frags [kt][mi][lane][4]
__device__ uint32_t g_lp[8 * 32 * 5 * 32 * 4];      // l A-frags [Bbg][kl][mi2][lane][4]
__device__ uint32_t g_ep[1024u * 4 * 4 * 32 * 4];   // ext A-frags [t][ek][mi][lane][4]
__device__ float g_c[B_DIM * H_DIM];
__device__ float g_l[B_DIM * 9 * H_DIM];
__device__ float g_f[B_DIM * H_DIM];
__device__ float g_o[B_DIM * H_DIM];
__device__ unsigned g_bar_count = 0;
__device__ volatile unsigned g_bar_gen = 0;

struct Params {
    const float* U[20];
    const float* W[20];
    const float* bb[20];
    const float* Y;
    const float* x[8];
    const float* W_a;
    const float* b_a;
};

// ---- fast activations (MUFU) ----
__device__ __forceinline__ float tanh_fast(float z) {
    float r; asm("tanh.approx.f32 %0, %1;" : "=f"(r) : "f"(z)); return r;
}
__device__ __forceinline__ float exp_fast(float z) {
    float r; asm("ex2.approx.ftz.f32 %0, %1;" : "=f"(r) : "f"(z * 1.4426950408889634f));
    return r;
}
__device__ __forceinline__ float sig_fast(float z) {
    float ex; asm("ex2.approx.ftz.f32 %0, %1;" : "=f"(ex) : "f"(z * -1.4426950408889634f));
    float r;  asm("rcp.approx.ftz.f32 %0, %1;" : "=f"(r) : "f"(1.0f + ex));
    return r;
}

__device__ __forceinline__ uint32_t cvt2h(float v0, float v1)
{
    const __half h0 = __float2half_rn(v0), h1 = __float2half_rn(v1);
    return ((uint32_t)__half_as_ushort(h1) << 16) | __half_as_ushort(h0);
}

__device__ __forceinline__ void mma_h(float* d, const uint32_t* a, uint32_t b0, uint32_t b1)
{
    asm volatile(
        "mma.sync.aligned.m16n8k16.row.col.f32.f16.f16.f32 "
        "{%0,%1,%2,%3}, {%4,%5,%6,%7}, {%8,%9}, {%0,%1,%2,%3};"
        : "+f"(d[0]), "+f"(d[1]), "+f"(d[2]), "+f"(d[3])
        : "r"(a[0]), "r"(a[1]), "r"(a[2]), "r"(a[3]), "r"(b0), "r"(b1));
}

// counting barrier with nanosleep backoff (empirically best variant)
__device__ __forceinline__ void grid_barrier()
{
    __syncthreads();
    if (threadIdx.x == 0) {
        __threadfence();
        unsigned gen = g_bar_gen;
        if (atomicAdd(&g_bar_count, 1u) == (unsigned)(gridDim.x - 1)) {
            g_bar_count = 0;
            __threadfence();
            g_bar_gen = gen + 1;
        } else {
            while (g_bar_gen == gen) { __nanosleep(32); }
            __threadfence();
        }
    }
    __syncthreads();
}

__device__ __forceinline__ int memA(int pt) { return pt == 0 ? 0 : (pt == 1 ? 1 : pt + 2); }
__device__ __forceinline__ int memB(int pt) { return pt == 0 ? 2 : (pt == 1 ? 3 : pt + 10); }

extern __shared__ float sm[];

__global__ __launch_bounds__(BLK, 1) void lstm_h7(Params p, float* __restrict__ out,
                                                  int seq_off, int write_hT)
{
    const int tid = threadIdx.x;
    const int bid = blockIdx.x;
    const int lane = tid & 31;
    const int wid = tid >> 5;
    const int gtid = bid * BLK + tid;
    char* smc = (char*)sm;
    float* bias_sm = (float*)(smc + BIAS_B);
    float* ub = (float*)(smc + UBUF_B);
    uint4* exts = (uint4*)(smc + EXTS_B);

    for (int i = gtid; i < 32 * 4 * 32 * 4; i += GRID * BLK) g_hp[i] = 0u;
    for (int i = gtid; i < 8 * 32 * 5 * 32 * 4; i += GRID * BLK) g_lp[i] = 0u;
    for (int i = gtid; i < B_DIM * H_DIM; i += GRID * BLK) g_c[i] = 0.0f;

    // ---- one-time: ext input A-frags (all t, single fp16) ----
    for (int idx = gtid; idx < T_DIM * 2048; idx += GRID * BLK) {
        const int t = idx >> 11;
        const int r = idx & 2047;
        const int b = r >> 5, q = (r & 31) * 2;
        float v0, v1;
        {
            const int qq = q;
            if (qq < 32) v0 = p.Y[((size_t)b * 32 + qq) * T_DIM + t];
            else if (qq < 56) { const int rr = qq - 32, xk = rr / 3, i2 = rr - 3 * xk;
                                v0 = p.x[xk][((size_t)b * 3 + i2) * T_DIM + t]; }
            else v0 = 0.0f;
        }
        {
            const int qq = q + 1;
            if (qq < 32) v1 = p.Y[((size_t)b * 32 + qq) * T_DIM + t];
            else if (qq < 56) { const int rr = qq - 32, xk = rr / 3, i2 = rr - 3 * xk;
                                v1 = p.x[xk][((size_t)b * 3 + i2) * T_DIM + t]; }
            else v1 = 0.0f;
        }
        const int lane2 = (b & 7) * 4 + ((q & 7) >> 1);
        const int slot = ((b >> 3) & 1) * 2 + ((q & 15) >> 3);
        g_ep[((((size_t)t * 4 + (q >> 4)) * 4 + (b >> 4)) * 32 + lane2) * 4 + slot] = cvt2h(v0, v1);
    }

    // ---- one-time: U pair-columns -> fp16 B-frags (smem) ----
    for (int e = tid; e < 80 * H_DIM; e += BLK) {
        const int s = e >> 9, j = e & 511;
        const int pq = bid * NPAIR + (s >> 1);
        const int pt = pq >> 9, c = pq & 511;
        const int m = (s & 1) ? memB(pt) : memA(pt);
        const float v = p.U[m][(size_t)j * H_DIM + c];
        const uint32_t off = (uint32_t)(s >> 3) * 8192u + (uint32_t)(j >> 4) * 256u
                           + (uint32_t)((s & 7) * 4 + ((j & 7) >> 1)) * 8u
                           + (uint32_t)((j & 15) >> 3) * 4u + (uint32_t)(j & 1) * 2u;
        *(unsigned short*)(smc + BF_B + off) = __half_as_ushort(__float2half_rn(v));
    }
    for (int e = tid; e < 2560; e += BLK) ((uint32_t*)(smc + BEXT_B))[e] = 0u;
    __syncthreads();
    for (int e = tid; e < 80 * 32; e += BLK) {
        const int s = e >> 5, i = e & 31;
        const int pq = bid * NPAIR + (s >> 1);
        const int pt = pq >> 9, c = pq & 511;
        const int m = (s & 1) ? memB(pt) : memA(pt);
        float v; int q;
        if (m < 4) { v = p.W[m][(size_t)i * H_DIM + c]; q = i; }
        else {
            if (i >= 3) continue;
            const int k = (m < 12) ? (m - 4) : (m - 12);
            const int xsel = (m < 12) ? ((k == 0) ? 0 : 1) : k;
            v = p.W[m][(size_t)i * H_DIM + c];
            q = 32 + xsel * 3 + i;
        }
        const uint32_t off = (uint32_t)(s >> 3) * 1024u + (uint32_t)(q >> 4) * 256u
                           + (uint32_t)((s & 7) * 4 + ((q & 7) >> 1)) * 8u
                           + (uint32_t)((q & 15) >> 3) * 4u + (uint32_t)(q & 1) * 2u;
        *(unsigned short*)(smc + BEXT_B + off) = __half_as_ushort(__float2half_rn(v));
    }
    for (int s = tid; s < 80; s += BLK) {
        const int pq = bid * NPAIR + (s >> 1);
        const int pt = pq >> 9, c = pq & 511;
        bias_sm[s] = p.bb[(s & 1) ? memB(pt) : memA(pt)][c];
    }
    {
        const int Bhg_ = bid & 15;
        for (int e = tid; e < 16384; e += BLK) {
            const int j = e >> 5, h2 = e & 31;
            const float v = p.W_a[(size_t)j * H_DIM + Bhg_ * 32 + h2];
            const uint32_t off = (uint32_t)(j >> 4) * 1024u + (uint32_t)(h2 >> 4) * 512u
                               + (uint32_t)((h2 & 7) * 4 + ((j & 7) >> 1)) * 16u
                               + ((((uint32_t)h2 >> 3) & 1) * 2 + (((uint32_t)j & 15) >> 3)) * 4u
                               + (uint32_t)(j & 1) * 2u;
            *(unsigned short*)(smc + WAS_B + off) = __half_as_ushort(__float2half_rn(v));
        }
    }
    grid_barrier();

    // stage ext frags for t=0
    for (int i = tid; i < 512; i += BLK) exts[i] = __ldg(((const uint4*)g_ep) + i);
    __syncthreads();

    // roles
    const int mi = wid & 3;
    const int nslot = wid >> 2;
    const int nt0 = (nslot == 0) ? 0 : (nslot == 1) ? 3 : (nslot == 2) ? 5 : 8;
    const int ntc = (nslot == 1 || nslot == 3) ? 2 : 3;
    const int g = lane >> 2, c4 = lane & 3;
    const int Bbg = bid >> 4, Bhg = bid & 15;

    for (int t = 0; t < T_DIM; t++) {
        // ================= PHASE A: sync-free, single-product =================
        float d[3][4];
        #pragma unroll
        for (int tt = 0; tt < 3; tt++) { d[tt][0]=0.f; d[tt][1]=0.f; d[tt][2]=0.f; d[tt][3]=0.f; }

        #pragma unroll 8
        for (int kt = 0; kt < 32; kt++) {
            const uint4 hv = __ldg((const uint4*)(g_hp + (((size_t)kt * 4 + mi) * 32 + lane) * 4));
            const uint32_t ah[4] = {hv.x, hv.z, hv.y, hv.w};
            #pragma unroll
            for (int tt = 0; tt < 3; tt++) {
                if (tt >= ntc) break;
                const uint2 bv = *(const uint2*)(smc + BF_B + (nt0 + tt) * 8192 + kt * 256 + lane * 8);
                mma_h(d[tt], ah, bv.x, bv.y);
            }
        }
        #pragma unroll
        for (int ek = 0; ek < 4; ek++) {
            const uint4 hv = exts[(ek * 4 + mi) * 32 + lane];
            const uint32_t ah[4] = {hv.x, hv.z, hv.y, hv.w};
            #pragma unroll
            for (int tt = 0; tt < 3; tt++) {
                if (tt >= ntc) break;
                const uint2 bv = *(const uint2*)(smc + BEXT_B + (nt0 + tt) * 1024 + ek * 256 + lane * 8);
                mma_h(d[tt], ah, bv.x, bv.y);
            }
        }

        // epilogue
        #pragma unroll
        for (int tt = 0; tt < 3; tt++) {
            if (tt >= ntc) break;
            const int cl = (nt0 + tt) * 8 + c4 * 2;
            const int pq = bid * NPAIR + (cl >> 1);
            const int pt = pq >> 9, c = pq & 511;
            const float bA = bias_sm[cl], bB = bias_sm[cl + 1];
            const int b0 = mi * 16 + g, b1 = b0 + 8;
            const float sA0 = sig_fast(d[tt][0] + bA), sA1 = sig_fast(d[tt][2] + bA);
            if (pt == 1) {
                g_f[b0 * H_DIM + c] = sA0;
                g_f[b1 * H_DIM + c] = sA1;
                g_o[b0 * H_DIM + c] = sig_fast(d[tt][1] + bB);
                g_o[b1 * H_DIM + c] = sig_fast(d[tt][3] + bB);
            } else {
                const int kk = (pt == 0) ? 0 : pt - 1;
                const float lv0 = sA0 * tanh_fast(d[tt][1] + bB);
                const float lv1 = sA1 * tanh_fast(d[tt][3] + bB);
                g_l[((size_t)b0 * 9 + kk) * H_DIM + c] = lv0;
                g_l[((size_t)b1 * 9 + kk) * H_DIM + c] = lv1;
                const float n0 = __shfl_xor_sync(0xFFFFFFFFu, lv0, 1);
                const float n1 = __shfl_xor_sync(0xFFFFFFFFu, lv1, 1);
                if (!(c4 & 1)) {   // even lane packs (this, next) column pair
                    const int cE = c;
                    const int lane2 = g * 4 + ((cE & 7) >> 1);
                    const int slot = (kk & 1) * 2 + ((cE & 15) >> 3);
                    const int mi2 = kk >> 1, j16 = cE >> 4;
                    g_lp[((((size_t)(mi * 2) * 32 + j16) * 5 + mi2) * 32 + lane2) * 4 + slot] = cvt2h(lv0, n0);
                    g_lp[((((size_t)(mi * 2 + 1) * 32 + j16) * 5 + mi2) * 32 + lane2) * 4 + slot] = cvt2h(lv1, n1);
                }
            }
        }
        grid_barrier();

        // ================= PHASE B + ext prefetch =================
        if (wid < 10) {
            float d2[2][4];
            #pragma unroll
            for (int n8 = 0; n8 < 2; n8++) { d2[n8][0]=0.f; d2[n8][1]=0.f; d2[n8][2]=0.f; d2[n8][3]=0.f; }
            const int mi2w = wid >> 1, n16 = wid & 1;
            #pragma unroll 8
            for (int kl = 0; kl < 32; kl++) {
                const uint4 hv = __ldg((const uint4*)(g_lp + ((((size_t)Bbg * 32 + kl) * 5 + mi2w) * 32 + lane) * 4));
                const uint32_t ah[4] = {hv.x, hv.z, hv.y, hv.w};
                const uint4 wv = *(const uint4*)(smc + WAS_B + kl * 1024 + n16 * 512 + lane * 16);
                mma_h(d2[0], ah, wv.x, wv.y);
                mma_h(d2[1], ah, wv.z, wv.w);
            }
            const int r0 = mi2w * 16 + g, r1 = r0 + 8;
            #pragma unroll
            for (int n8 = 0; n8 < 2; n8++) {
                const int n0 = n16 * 16 + n8 * 8 + c4 * 2;
                ub[r0 * 32 + n0]     = d2[n8][0];
                ub[r0 * 32 + n0 + 1] = d2[n8][1];
                if (r1 < 72) {
                    ub[r1 * 32 + n0]     = d2[n8][2];
                    ub[r1 * 32 + n0 + 1] = d2[n8][3];
                }
            }
        } else if (t + 1 < T_DIM) {
            // warps 10..15: stage ext A-frags for step t+1
            const uint4* src = ((const uint4*)g_ep) + (size_t)(t + 1) * 512;
            for (int i = tid - 320; i < 512; i += 192) exts[i] = __ldg(src + i);
        }
        __syncthreads();

        // combine + packed fp16 h store
        if (tid < 256) {
            const int bl2 = tid >> 5, hl2 = tid & 31;
            const int b = Bbg * 8 + bl2, h = Bhg * 32 + hl2;
            const float c_old = g_c[b * H_DIM + h];
            const float ba = p.b_a[h];
            float uu[9], mx = -1e30f;
            #pragma unroll
            for (int k = 0; k < 9; k++) {
                const float u = ub[(k * 8 + bl2) * 32 + hl2];
                uu[k] = tanh_fast(fmaf(u, c_old, ba));
                mx = fmaxf(mx, uu[k]);
            }
            float se = 0.0f, L = 0.0f;
            #pragma unroll
            for (int k = 0; k < 9; k++) {
                const float e = exp_fast(uu[k] - mx);
                se += e;
                L = fmaf(e, __ldcg(g_l + ((size_t)b * 9 + k) * H_DIM + h), L);
            }
            L /= se;
            const float cn = fmaf(__ldcg(g_f + b * H_DIM + h), c_old, L);
            const float hn = __ldcg(g_o + b * H_DIM + h) * tanh_fast(cn);
            g_c[b * H_DIM + h] = cn;

            const float nh = __shfl_xor_sync(0xFFFFFFFFu, hn, 1);
            if (!(hl2 & 1)) {
                const int hE = h;
                const int lane2 = (b & 7) * 4 + ((hE & 7) >> 1);
                const int slot = ((b >> 3) & 1) * 2 + ((hE & 15) >> 3);
                g_hp[(((size_t)(hE >> 4) * 4 + (b >> 4)) * 32 + lane2) * 4 + slot] = cvt2h(hn, nh);
            }

            out[(size_t)seq_off + ((size_t)b * T_DIM + t) * H_DIM + h] = hn;
            if (write_hT && t == T_DIM - 1)
                out[(size_t)b * H_DIM + h] = hn;
        }
        grid_barrier();
    }
}

// ---------------------------------------------------------------------
extern "C" void kernel_launch(void* const* d_in, const int* in_sizes, int n_in,
                              void* d_out, int out_size)
{
    Params p;
    p.Y = (const float*)d_in[0];
    for (int j = 0; j < 8; j++) p.x[j] = (const float*)d_in[1 + j];
    const float* W_i = (const float*)d_in[9],  *U_i = (const float*)d_in[10], *b_i = (const float*)d_in[11];
    const float* W_f = (const float*)d_in[12], *U_f = (const float*)d_in[13], *b_f = (const float*)d_in[14];
    const float* W_c = (const float*)d_in[15], *U_c = (const float*)d_in[16], *b_c = (const float*)d_in[17];
    const float* W_o = (const float*)d_in[18], *U_o = (const float*)d_in[19], *b_o = (const float*)d_in[20];
    const float* W_i_x = (const float*)d_in[21], *U_i_x = (const float*)d_in[22], *b_i_x = (const float*)d_in[23];
    const float* W_c_x = (const float*)d_in[24], *U_c_x = (const float*)d_in[25], *b_c_x = (const float*)d_in[26];
    p.W_a = (const float*)d_in[27];
    p.b_a = (const float*)d_in[28];

    p.U[0] = U_i; p.U[1] = U_f; p.U[2] = U_c; p.U[3] = U_o;
    p.W[0] = W_i; p.W[1] = W_f; p.W[2] = W_c; p.W[3] = W_o;
    p.bb[0] = b_i; p.bb[1] = b_f; p.bb[2] = b_c; p.bb[3] = b_o;
    for (int k = 0; k < 8; k++) {
        p.U[4 + k]  = U_i_x + (size_t)k * H_DIM * H_DIM;
        p.U[12 + k] = U_c_x + (size_t)k * H_DIM * H_DIM;
        p.W[4 + k]  = W_i_x + (size_t)k * 3 * H_DIM;
        p.W[12 + k] = W_c_x + (size_t)k * 3 * H_DIM;
        p.bb[4 + k]  = b_i_x + (size_t)k * H_DIM;
        p.bb[12 + k] = b_c_x + (size_t)k * H_DIM;
    }

    float* out = (float*)d_out;
    const int full = B_DIM * H_DIM + B_DIM * T_DIM * H_DIM;
    const int seq_off = (out_size >= full) ? (B_DIM * H_DIM) : 0;
    const int write_hT = (seq_off != 0) ? 1 : 0;

    static int configured = 0;
    if (!configured) {
        cudaFuncSetAttribute(lstm_h7, cudaFuncAttributeMaxDynamicSharedMemorySize, SMEM_BYTES);
        configured = 1;
    }
    lstm_h7<<<GRID, BLK, SMEM_BYTES>>>(p, out, seq_off, write_hT);
}